// round 8
// baseline (speedup 1.0000x reference)
#include <cuda_runtime.h>
#include <cuda_bf16.h>
#include <cstdint>
#include <cstddef>

// Problem constants (LowFER)
#define BB 256          // batch
#define VV 400000       // vocab (= 3125 * 128)
#define D1 128
#define PP 64           // D1/2
#define KK 30
#define TT 20
#define BN_EPS 1e-5f
#define FACTOR 0.040824829046386304f   // 1/sqrt(K*T)

// x as bf16, transposed [b][k], padded row stride 34 bf16 (17 u32).
// __device__ globals are zero-initialized; k=30..33 stay 0.
#define XSTR_U32 17
__device__ uint32_t g_xbf32[BB * XSTR_U32];

// staging tile stride (floats): 132 = 33 float4
#define TSTR 132

// ---------------- helpers ----------------
__device__ __forceinline__ uint32_t pack_bf16x2(float lo, float hi) {
    uint32_t r;
    asm("cvt.rn.bf16x2.f32 %0, %1, %2;" : "=r"(r) : "f"(hi), "f"(lo));
    return r;
}
// sigmoid via ex2 + rcp (high accuracy, 2 MUFU)
__device__ __forceinline__ float fast_sigmoid(float z) {
    float e;
    asm("ex2.approx.f32 %0, %1;" : "=f"(e) : "f"(-z * 1.4426950408889634f));
    float r;
    asm("rcp.approx.f32 %0, %1;" : "=f"(r) : "f"(1.0f + e));
    return r;
}
// m16n8k16 bf16 x bf16 -> f32 (sm_80+ base feature)
__device__ __forceinline__ void mma_bf16(float* c, const uint32_t* a, const uint32_t* b) {
    asm volatile(
        "mma.sync.aligned.m16n8k16.row.col.f32.bf16.bf16.f32 "
        "{%0,%1,%2,%3}, {%4,%5,%6,%7}, {%8,%9}, {%0,%1,%2,%3};"
        : "+f"(c[0]), "+f"(c[1]), "+f"(c[2]), "+f"(c[3])
        : "r"(a[0]), "r"(a[1]), "r"(a[2]), "r"(a[3]), "r"(b[0]), "r"(b[1]));
}

// ---------------- Kernel 1: compute x, store as bf16 [b][k] padded ----------------
__global__ void prep_kernel(const int* __restrict__ e1_idx, const int* __restrict__ r_idx,
                            const float* __restrict__ E,   const float* __restrict__ R,
                            const float* __restrict__ proj, const int* __restrict__ idx,
                            const float* __restrict__ g0, const float* __restrict__ b0,
                            const float* __restrict__ m0, const float* __restrict__ v0,
                            const float* __restrict__ g1, const float* __restrict__ b1,
                            const float* __restrict__ m1, const float* __restrict__ v1)
{
    __shared__ float e1s[D1];
    __shared__ float rrs[D1];
    __shared__ float ses[PP];
    __shared__ float srs[PP];

    const int t = threadIdx.x;     // 0..63
    const int b = blockIdx.x;      // 0..255

    const int ei = e1_idx[b];
    const int ri = r_idx[b];

    #pragma unroll
    for (int j = 0; j < 2; j++) {
        const int d = t + j * 64;
        float ev = E[(size_t)ei * D1 + d];
        e1s[d] = (ev - m0[d]) * rsqrtf(v0[d] + BN_EPS) * g0[d] + b0[d];
        rrs[d] = R[(size_t)ri * D1 + d];
    }
    __syncthreads();

    float sa = 0.f, sb = 0.f;
    #pragma unroll 4
    for (int d = 0; d < D1; d++) {
        const float p = proj[d * PP + t];
        sa = fmaf(e1s[d], p, sa);
        sb = fmaf(rrs[d], p, sb);
    }
    ses[t] = sa;
    srs[t] = sb;
    __syncthreads();

    float x = 0.f;
    if (t < KK) {
        float y = 0.f;
        #pragma unroll
        for (int tt = 0; tt < TT; tt++) {
            const int ia = idx[(t * TT + tt) * 2 + 0];
            const int ib = idx[(t * TT + tt) * 2 + 1];
            y = fmaf(ses[ia], srs[ib], y);
        }
        y *= FACTOR;
        const float sg = (y > 0.f) ? 1.f : ((y < 0.f) ? -1.f : 0.f);
        x = sg * sqrtf(fabsf(y) + 1e-12f);
    }

    if (t < 32) {
        float ss = x * x;
        #pragma unroll
        for (int o = 16; o; o >>= 1) ss += __shfl_xor_sync(0xffffffffu, ss, o);
        const float nrm = sqrtf(ss);
        float xn = 0.f;
        if (t < KK) {
            xn = x / fmaxf(nrm, 1e-12f);
            xn = (xn - m1[t]) * rsqrtf(v1[t] + BN_EPS) * g1[t] + b1[t];
        }
        // bf16 write, transposed layout [b][k], k in [0,32); 30,31 -> 0
        __nv_bfloat16* xb = reinterpret_cast<__nv_bfloat16*>(g_xbf32);
        xb[b * (2 * XSTR_U32) + t] = __float2bfloat16(xn);
    }
}

// ---------------- Kernel 2: warp-level bf16 MMA + transposed-store epilogue ------
// CTA: 128 threads (4 warps). M=128 v (32 per warp), N=256 b in 8 passes of 32,
// K=32 (k 30/31 zero). Epilogue: sigmoid -> STS to sT[b][v] (conflict-free) ->
// per-warp LDS.128 of whole b-rows -> single contiguous 512B STG.128 per row.
__global__ __launch_bounds__(128, 4)
void mma_kernel(const float* __restrict__ E, float* __restrict__ out)
{
    __shared__ uint32_t sE32[128 * 16];        // E tile: [v][k-pairs], 8 KB
    __shared__ uint32_t sX32[BB * XSTR_U32];   // x tile: [b][k-pairs, pad 17], 17 KB
    __shared__ float    sT[32 * TSTR];         // staging: [b_local][v_local], 16.9 KB

    const int tid  = threadIdx.x;
    const int wid  = tid >> 5;
    const int lane = tid & 31;
    const int grp  = lane >> 2;   // 0..7
    const int qid  = lane & 3;    // 0..3

    const int v0 = blockIdx.x * 128;

    // Build sE: one row per thread; k cols 0..29 real, 30/31 zero
    {
        const int r = tid;
        const float4* p = reinterpret_cast<const float4*>(E + (size_t)(v0 + r) * D1);
        float e[32];
        #pragma unroll
        for (int q = 0; q < 7; q++) {
            float4 f = p[q];
            e[q * 4 + 0] = f.x; e[q * 4 + 1] = f.y;
            e[q * 4 + 2] = f.z; e[q * 4 + 3] = f.w;
        }
        float2 f2 = reinterpret_cast<const float2*>(p)[14];
        e[28] = f2.x; e[29] = f2.y; e[30] = 0.f; e[31] = 0.f;
        #pragma unroll
        for (int j = 0; j < 16; j++)
            sE32[r * 16 + j] = pack_bf16x2(e[2 * j], e[2 * j + 1]);
    }
    // Copy x tile (17408 B) straight from device global
    #pragma unroll
    for (int i = tid; i < BB * XSTR_U32; i += 128)
        sX32[i] = g_xbf32[i];
    __syncthreads();

    // A fragments, persistent: [mtile][kchunk][reg]
    uint32_t a[2][2][4];
    {
        const int r0 = wid * 32 + grp;
        #pragma unroll
        for (int mt = 0; mt < 2; mt++) {
            #pragma unroll
            for (int kc = 0; kc < 2; kc++) {
                const int rr = r0 + mt * 16;
                const int cp = kc * 8 + qid;   // k-pair index
                a[mt][kc][0] = sE32[rr * 16 + cp];
                a[mt][kc][1] = sE32[(rr + 8) * 16 + cp];
                a[mt][kc][2] = sE32[rr * 16 + cp + 4];
                a[mt][kc][3] = sE32[(rr + 8) * 16 + cp + 4];
            }
        }
    }

    const int vbase = wid * 32 + grp;   // v_local of c0/c1; +8 for c2/c3, +16 per mt

    #pragma unroll 1
    for (int pass = 0; pass < 8; pass++) {
        const int bp = pass * 32;

        // B fragments for this 32-b slab: [ntile][kchunk][reg]
        uint32_t bf[4][2][2];
        #pragma unroll
        for (int nt = 0; nt < 4; nt++) {
            const int bcol = bp + nt * 8 + grp;
            #pragma unroll
            for (int kc = 0; kc < 2; kc++) {
                bf[nt][kc][0] = sX32[bcol * XSTR_U32 + kc * 8 + qid];
                bf[nt][kc][1] = sX32[bcol * XSTR_U32 + kc * 8 + qid + 4];
            }
        }

        float acc[2][4][4];
        #pragma unroll
        for (int mt = 0; mt < 2; mt++)
            #pragma unroll
            for (int nt = 0; nt < 4; nt++)
                #pragma unroll
                for (int j = 0; j < 4; j++) acc[mt][nt][j] = 0.f;

        #pragma unroll
        for (int kc = 0; kc < 2; kc++)
            #pragma unroll
            for (int mt = 0; mt < 2; mt++)
                #pragma unroll
                for (int nt = 0; nt < 4; nt++)
                    mma_bf16(acc[mt][nt], a[mt][kc], bf[nt][kc]);

        // Stage sigmoid(acc) into sT[b_local][v_local].
        // STS bank = (qid*8 + grp) mod 32 -> conflict-free within warp.
        #pragma unroll
        for (int mt = 0; mt < 2; mt++) {
            const int vl = vbase + mt * 16;
            #pragma unroll
            for (int nt = 0; nt < 4; nt++) {
                const int bl = nt * 8 + qid * 2;
                const float* c = acc[mt][nt];
                sT[(bl + 0) * TSTR + vl]     = fast_sigmoid(c[0]);
                sT[(bl + 1) * TSTR + vl]     = fast_sigmoid(c[1]);
                sT[(bl + 0) * TSTR + vl + 8] = fast_sigmoid(c[2]);
                sT[(bl + 1) * TSTR + vl + 8] = fast_sigmoid(c[3]);
            }
        }
        __syncthreads();

        // Drain: warp w handles b-rows [w*8, w*8+8); each row = 128 v = one
        // LDS.128 + one fully-coalesced 512B STG.128 across the warp.
        {
            const float4* sT4 = reinterpret_cast<const float4*>(sT);
            #pragma unroll
            for (int j = 0; j < 8; j++) {
                const int r = wid * 8 + j;
                const float4 val = sT4[r * (TSTR / 4) + lane];
                *reinterpret_cast<float4*>(
                    &out[(size_t)(bp + r) * VV + v0 + lane * 4]) = val;
            }
        }
        __syncthreads();
    }
}

// ---------------- launch ----------------
extern "C" void kernel_launch(void* const* d_in, const int* in_sizes, int n_in,
                              void* d_out, int out_size)
{
    (void)in_sizes; (void)n_in; (void)out_size;
    const int*   e1_idx = (const int*)  d_in[0];
    const int*   r_idx  = (const int*)  d_in[1];
    const float* E      = (const float*)d_in[2];
    const float* R      = (const float*)d_in[3];
    const float* proj   = (const float*)d_in[4];
    const int*   idx    = (const int*)  d_in[5];
    const float* g0     = (const float*)d_in[6];
    const float* b0     = (const float*)d_in[7];
    const float* m0     = (const float*)d_in[8];
    const float* v0     = (const float*)d_in[9];
    const float* g1     = (const float*)d_in[10];
    const float* b1     = (const float*)d_in[11];
    const float* m1     = (const float*)d_in[12];
    const float* v1     = (const float*)d_in[13];
    float*       out    = (float*)d_out;

    prep_kernel<<<BB, 64>>>(e1_idx, r_idx, E, R, proj, idx,
                            g0, b0, m0, v0, g1, b1, m1, v1);

    mma_kernel<<<VV / 128, 128>>>(E, out);   // 3125 CTAs
}

// round 10
// speedup vs baseline: 1.0606x; 1.0606x over previous
#include <cuda_runtime.h>
#include <cuda_bf16.h>
#include <cstdint>
#include <cstddef>

// Problem constants (LowFER)
#define BB 256          // batch
#define VV 400000       // vocab (= 3125 * 128)
#define D1 128
#define PP 64           // D1/2
#define KK 30
#define TT 20
#define BN_EPS 1e-5f
#define FACTOR 0.040824829046386304f   // 1/sqrt(K*T)

// x as bf16, transposed [b][k], padded row stride 34 bf16 (17 u32).
// __device__ globals are zero-initialized; k=30..33 stay 0.
#define XSTR_U32 17
__device__ uint32_t g_xbf32[BB * XSTR_U32];

// ---------------- helpers ----------------
__device__ __forceinline__ uint32_t pack_bf16x2(float lo, float hi) {
    uint32_t r;
    asm("cvt.rn.bf16x2.f32 %0, %1, %2;" : "=r"(r) : "f"(hi), "f"(lo));
    return r;
}
// sigmoid via ex2 + rcp (high accuracy, 2 MUFU)
__device__ __forceinline__ float fast_sigmoid(float z) {
    float e;
    asm("ex2.approx.f32 %0, %1;" : "=f"(e) : "f"(-z * 1.4426950408889634f));
    float r;
    asm("rcp.approx.f32 %0, %1;" : "=f"(r) : "f"(1.0f + e));
    return r;
}
// m16n8k16 bf16 x bf16 -> f32 (sm_80+ base feature)
__device__ __forceinline__ void mma_bf16(float* c, const uint32_t* a, const uint32_t* b) {
    asm volatile(
        "mma.sync.aligned.m16n8k16.row.col.f32.bf16.bf16.f32 "
        "{%0,%1,%2,%3}, {%4,%5,%6,%7}, {%8,%9}, {%0,%1,%2,%3};"
        : "+f"(c[0]), "+f"(c[1]), "+f"(c[2]), "+f"(c[3])
        : "r"(a[0]), "r"(a[1]), "r"(a[2]), "r"(a[3]), "r"(b[0]), "r"(b[1]));
}

// ---------------- Kernel 1: compute x, store as bf16 [b][k] padded ----------------
__global__ void prep_kernel(const int* __restrict__ e1_idx, const int* __restrict__ r_idx,
                            const float* __restrict__ E,   const float* __restrict__ R,
                            const float* __restrict__ proj, const int* __restrict__ idx,
                            const float* __restrict__ g0, const float* __restrict__ b0,
                            const float* __restrict__ m0, const float* __restrict__ v0,
                            const float* __restrict__ g1, const float* __restrict__ b1,
                            const float* __restrict__ m1, const float* __restrict__ v1)
{
    __shared__ float e1s[D1];
    __shared__ float rrs[D1];
    __shared__ float ses[PP];
    __shared__ float srs[PP];

    const int t = threadIdx.x;     // 0..63
    const int b = blockIdx.x;      // 0..255

    const int ei = e1_idx[b];
    const int ri = r_idx[b];

    #pragma unroll
    for (int j = 0; j < 2; j++) {
        const int d = t + j * 64;
        float ev = E[(size_t)ei * D1 + d];
        e1s[d] = (ev - m0[d]) * rsqrtf(v0[d] + BN_EPS) * g0[d] + b0[d];
        rrs[d] = R[(size_t)ri * D1 + d];
    }
    __syncthreads();

    float sa = 0.f, sb = 0.f;
    #pragma unroll 4
    for (int d = 0; d < D1; d++) {
        const float p = proj[d * PP + t];
        sa = fmaf(e1s[d], p, sa);
        sb = fmaf(rrs[d], p, sb);
    }
    ses[t] = sa;
    srs[t] = sb;
    __syncthreads();

    float x = 0.f;
    if (t < KK) {
        float y = 0.f;
        #pragma unroll
        for (int tt = 0; tt < TT; tt++) {
            const int ia = idx[(t * TT + tt) * 2 + 0];
            const int ib = idx[(t * TT + tt) * 2 + 1];
            y = fmaf(ses[ia], srs[ib], y);
        }
        y *= FACTOR;
        const float sg = (y > 0.f) ? 1.f : ((y < 0.f) ? -1.f : 0.f);
        x = sg * sqrtf(fabsf(y) + 1e-12f);
    }

    if (t < 32) {
        float ss = x * x;
        #pragma unroll
        for (int o = 16; o; o >>= 1) ss += __shfl_xor_sync(0xffffffffu, ss, o);
        const float nrm = sqrtf(ss);
        float xn = 0.f;
        if (t < KK) {
            xn = x / fmaxf(nrm, 1e-12f);
            xn = (xn - m1[t]) * rsqrtf(v1[t] + BN_EPS) * g1[t] + b1[t];
        }
        // bf16 write, transposed layout [b][k], k in [0,32); 30,31 -> 0
        __nv_bfloat16* xb = reinterpret_cast<__nv_bfloat16*>(g_xbf32);
        xb[b * (2 * XSTR_U32) + t] = __float2bfloat16(xn);
    }
}

// ---------------- Kernel 2: warp-level bf16 MMA + WARP-PRIVATE staged stores -----
// CTA: 128 threads (4 warps). M=128 v (32 per warp), N=256 b in 8 passes of 32.
// Epilogue per warp pass: sigmoid -> STS into the warp's PRIVATE 32b x 32v tile
// (XOR-swizzled, conflict-free) -> __syncwarp -> per-row LDS.32 (conflict-free)
// -> full-128B-line STG.32. No __syncthreads in the loop: warps overlap freely.
__global__ __launch_bounds__(128, 4)
void mma_kernel(const float* __restrict__ E, float* __restrict__ out)
{
    __shared__ uint32_t sE32[128 * 16];        // E tile: [v][k-pairs], 8 KB
    __shared__ uint32_t sX32[BB * XSTR_U32];   // x tile: [b][k-pairs, pad 17], 17 KB
    __shared__ float    sW[4][32 * 32];        // per-warp staging, 4 x 4 KB

    const int tid  = threadIdx.x;
    const int wid  = tid >> 5;
    const int lane = tid & 31;
    const int grp  = lane >> 2;   // 0..7
    const int qid  = lane & 3;    // 0..3

    const int v0 = blockIdx.x * 128;

    // Build sE: one row per thread; k cols 0..29 real, 30/31 zero
    {
        const int r = tid;
        const float4* p = reinterpret_cast<const float4*>(E + (size_t)(v0 + r) * D1);
        float e[32];
        #pragma unroll
        for (int q = 0; q < 7; q++) {
            float4 f = p[q];
            e[q * 4 + 0] = f.x; e[q * 4 + 1] = f.y;
            e[q * 4 + 2] = f.z; e[q * 4 + 3] = f.w;
        }
        float2 f2 = reinterpret_cast<const float2*>(p)[14];
        e[28] = f2.x; e[29] = f2.y; e[30] = 0.f; e[31] = 0.f;
        #pragma unroll
        for (int j = 0; j < 16; j++)
            sE32[r * 16 + j] = pack_bf16x2(e[2 * j], e[2 * j + 1]);
    }
    // Copy x tile (17408 B) straight from device global
    #pragma unroll
    for (int i = tid; i < BB * XSTR_U32; i += 128)
        sX32[i] = g_xbf32[i];
    __syncthreads();

    // A fragments, persistent: [mtile][kchunk][reg]
    uint32_t a[2][2][4];
    {
        const int r0 = wid * 32 + grp;
        #pragma unroll
        for (int mt = 0; mt < 2; mt++) {
            #pragma unroll
            for (int kc = 0; kc < 2; kc++) {
                const int rr = r0 + mt * 16;
                const int cp = kc * 8 + qid;   // k-pair index
                a[mt][kc][0] = sE32[rr * 16 + cp];
                a[mt][kc][1] = sE32[(rr + 8) * 16 + cp];
                a[mt][kc][2] = sE32[rr * 16 + cp + 4];
                a[mt][kc][3] = sE32[(rr + 8) * 16 + cp + 4];
            }
        }
    }

    float* w = sW[wid];
    const int sw = qid << 3;              // STS swizzle key (= (b_local>>1)&3 << 3)

    #pragma unroll 1
    for (int pass = 0; pass < 8; pass++) {
        const int bp = pass * 32;

        // B fragments for this 32-b slab: [ntile][kchunk][reg]
        uint32_t bf[4][2][2];
        #pragma unroll
        for (int nt = 0; nt < 4; nt++) {
            const int bcol = bp + nt * 8 + grp;
            #pragma unroll
            for (int kc = 0; kc < 2; kc++) {
                bf[nt][kc][0] = sX32[bcol * XSTR_U32 + kc * 8 + qid];
                bf[nt][kc][1] = sX32[bcol * XSTR_U32 + kc * 8 + qid + 4];
            }
        }

        float acc[2][4][4];
        #pragma unroll
        for (int mt = 0; mt < 2; mt++)
            #pragma unroll
            for (int nt = 0; nt < 4; nt++)
                #pragma unroll
                for (int j = 0; j < 4; j++) acc[mt][nt][j] = 0.f;

        #pragma unroll
        for (int kc = 0; kc < 2; kc++)
            #pragma unroll
            for (int mt = 0; mt < 2; mt++)
                #pragma unroll
                for (int nt = 0; nt < 4; nt++)
                    mma_bf16(acc[mt][nt], a[mt][kc], bf[nt][kc]);

        // Stage sigmoid(acc) into the warp-private tile, XOR-swizzled.
        // Addr = b_local*32 + (v_local ^ (qid<<3)): banks injective per STS.
        #pragma unroll
        for (int mt = 0; mt < 2; mt++) {
            const int vl = grp + mt * 16;        // v_local of c0/c1; +8 for c2/c3
            #pragma unroll
            for (int nt = 0; nt < 4; nt++) {
                const int bl = nt * 8 + qid * 2; // b_local of c0/c2; +1 for c1/c3
                const float* c = acc[mt][nt];
                w[(bl + 0) * 32 + (vl ^ sw)]       = fast_sigmoid(c[0]);
                w[(bl + 1) * 32 + (vl ^ sw)]       = fast_sigmoid(c[1]);
                w[(bl + 0) * 32 + ((vl + 8) ^ sw)] = fast_sigmoid(c[2]);
                w[(bl + 1) * 32 + ((vl + 8) ^ sw)] = fast_sigmoid(c[3]);
            }
        }
        __syncwarp();

        // Drain: row j (b_local) -> one conflict-free LDS.32 + one full-line
        // 128B STG.32 (32 consecutive v across lanes).
        {
            float* obase = out + (size_t)bp * VV + v0 + wid * 32 + lane;
            #pragma unroll
            for (int j = 0; j < 32; j++) {
                const int q = (j >> 1) & 3;
                obase[(size_t)j * VV] = w[j * 32 + (lane ^ (q << 3))];
            }
        }
        __syncwarp();
    }
}

// ---------------- launch ----------------
extern "C" void kernel_launch(void* const* d_in, const int* in_sizes, int n_in,
                              void* d_out, int out_size)
{
    (void)in_sizes; (void)n_in; (void)out_size;
    const int*   e1_idx = (const int*)  d_in[0];
    const int*   r_idx  = (const int*)  d_in[1];
    const float* E      = (const float*)d_in[2];
    const float* R      = (const float*)d_in[3];
    const float* proj   = (const float*)d_in[4];
    const int*   idx    = (const int*)  d_in[5];
    const float* g0     = (const float*)d_in[6];
    const float* b0     = (const float*)d_in[7];
    const float* m0     = (const float*)d_in[8];
    const float* v0     = (const float*)d_in[9];
    const float* g1     = (const float*)d_in[10];
    const float* b1     = (const float*)d_in[11];
    const float* m1     = (const float*)d_in[12];
    const float* v1     = (const float*)d_in[13];
    float*       out    = (float*)d_out;

    prep_kernel<<<BB, 64>>>(e1_idx, r_idx, E, R, proj, idx,
                            g0, b0, m0, v0, g1, b1, m1, v1);

    mma_kernel<<<VV / 128, 128>>>(E, out);   // 3125 CTAs
}

// round 11
// speedup vs baseline: 1.1032x; 1.0401x over previous
#include <cuda_runtime.h>
#include <cuda_bf16.h>
#include <cstdint>
#include <cstddef>

// Problem constants (LowFER)
#define BB 256          // batch
#define VV 400000       // vocab (= 3125 * 128)
#define D1 128
#define PP 64           // D1/2
#define KK 30
#define TT 20
#define BN_EPS 1e-5f
#define FACTOR 0.040824829046386304f   // 1/sqrt(K*T)

// x as bf16, transposed [b][k], padded row stride 34 bf16 (17 u32).
// __device__ globals are zero-initialized; k=30..33 stay 0.
#define XSTR_U32 17
__device__ uint32_t g_xbf32[BB * XSTR_U32];

// ---------------- helpers ----------------
__device__ __forceinline__ uint32_t pack_bf16x2(float lo, float hi) {
    uint32_t r;
    asm("cvt.rn.bf16x2.f32 %0, %1, %2;" : "=r"(r) : "f"(hi), "f"(lo));
    return r;
}
// sigmoid via ex2 + rcp (high accuracy, 2 MUFU)
__device__ __forceinline__ float fast_sigmoid(float z) {
    float e;
    asm("ex2.approx.f32 %0, %1;" : "=f"(e) : "f"(-z * 1.4426950408889634f));
    float r;
    asm("rcp.approx.f32 %0, %1;" : "=f"(r) : "f"(1.0f + e));
    return r;
}
// streaming store (evict-first): output is write-once
__device__ __forceinline__ void stcs128(float* p, float4 v) {
    asm volatile("st.global.cs.v4.f32 [%0], {%1,%2,%3,%4};"
                 :: "l"(p), "f"(v.x), "f"(v.y), "f"(v.z), "f"(v.w) : "memory");
}
// m16n8k16 bf16 x bf16 -> f32 (sm_80+ base feature)
__device__ __forceinline__ void mma_bf16(float* c, const uint32_t* a, const uint32_t* b) {
    asm volatile(
        "mma.sync.aligned.m16n8k16.row.col.f32.bf16.bf16.f32 "
        "{%0,%1,%2,%3}, {%4,%5,%6,%7}, {%8,%9}, {%0,%1,%2,%3};"
        : "+f"(c[0]), "+f"(c[1]), "+f"(c[2]), "+f"(c[3])
        : "r"(a[0]), "r"(a[1]), "r"(a[2]), "r"(a[3]), "r"(b[0]), "r"(b[1]));
}

// ---------------- Kernel 1: compute x, store as bf16 [b][k] padded ----------------
__global__ void prep_kernel(const int* __restrict__ e1_idx, const int* __restrict__ r_idx,
                            const float* __restrict__ E,   const float* __restrict__ R,
                            const float* __restrict__ proj, const int* __restrict__ idx,
                            const float* __restrict__ g0, const float* __restrict__ b0,
                            const float* __restrict__ m0, const float* __restrict__ v0,
                            const float* __restrict__ g1, const float* __restrict__ b1,
                            const float* __restrict__ m1, const float* __restrict__ v1)
{
    __shared__ float e1s[D1];
    __shared__ float rrs[D1];
    __shared__ float ses[PP];
    __shared__ float srs[PP];

    const int t = threadIdx.x;     // 0..63
    const int b = blockIdx.x;      // 0..255

    const int ei = e1_idx[b];
    const int ri = r_idx[b];

    #pragma unroll
    for (int j = 0; j < 2; j++) {
        const int d = t + j * 64;
        float ev = E[(size_t)ei * D1 + d];
        e1s[d] = (ev - m0[d]) * rsqrtf(v0[d] + BN_EPS) * g0[d] + b0[d];
        rrs[d] = R[(size_t)ri * D1 + d];
    }
    __syncthreads();

    float sa = 0.f, sb = 0.f;
    #pragma unroll 4
    for (int d = 0; d < D1; d++) {
        const float p = proj[d * PP + t];
        sa = fmaf(e1s[d], p, sa);
        sb = fmaf(rrs[d], p, sb);
    }
    ses[t] = sa;
    srs[t] = sb;
    __syncthreads();

    float x = 0.f;
    if (t < KK) {
        float y = 0.f;
        #pragma unroll
        for (int tt = 0; tt < TT; tt++) {
            const int ia = idx[(t * TT + tt) * 2 + 0];
            const int ib = idx[(t * TT + tt) * 2 + 1];
            y = fmaf(ses[ia], srs[ib], y);
        }
        y *= FACTOR;
        const float sg = (y > 0.f) ? 1.f : ((y < 0.f) ? -1.f : 0.f);
        x = sg * sqrtf(fabsf(y) + 1e-12f);
    }

    if (t < 32) {
        float ss = x * x;
        #pragma unroll
        for (int o = 16; o; o >>= 1) ss += __shfl_xor_sync(0xffffffffu, ss, o);
        const float nrm = sqrtf(ss);
        float xn = 0.f;
        if (t < KK) {
            xn = x / fmaxf(nrm, 1e-12f);
            xn = (xn - m1[t]) * rsqrtf(v1[t] + BN_EPS) * g1[t] + b1[t];
        }
        // bf16 write, transposed layout [b][k], k in [0,32); 30,31 -> 0
        __nv_bfloat16* xb = reinterpret_cast<__nv_bfloat16*>(g_xbf32);
        xb[b * (2 * XSTR_U32) + t] = __float2bfloat16(xn);
    }
}

// ---------------- Kernel 2: warp-level bf16 MMA + WARP-PRIVATE staged stores -----
// CTA: 128 threads (4 warps). M=128 v (32 per warp), N=256 b in 8 passes of 32.
// Per warp pass: MMA -> sigmoid -> STS into private 32b x 32v tile (XOR swizzle,
// conflict-free) -> __syncwarp -> drain as 8 x (LDS.128 + STG.128), each STG
// writing 4 full 128B lines. 5 CTAs/SM for latency hiding.
__global__ __launch_bounds__(128, 5)
void mma_kernel(const float* __restrict__ E, float* __restrict__ out)
{
    __shared__ uint32_t sE32[128 * 16];        // E tile: [v][k-pairs], 8 KB
    __shared__ uint32_t sX32[BB * XSTR_U32];   // x tile: [b][k-pairs, pad 17], 17 KB
    __shared__ float    sW[4][32 * 32];        // per-warp staging, 4 x 4 KB

    const int tid  = threadIdx.x;
    const int wid  = tid >> 5;
    const int lane = tid & 31;
    const int grp  = lane >> 2;   // 0..7
    const int qid  = lane & 3;    // 0..3

    const int v0 = blockIdx.x * 128;

    // Build sE: one row per thread; k cols 0..29 real, 30/31 zero
    {
        const int r = tid;
        const float4* p = reinterpret_cast<const float4*>(E + (size_t)(v0 + r) * D1);
        float e[32];
        #pragma unroll
        for (int q = 0; q < 7; q++) {
            float4 f = p[q];
            e[q * 4 + 0] = f.x; e[q * 4 + 1] = f.y;
            e[q * 4 + 2] = f.z; e[q * 4 + 3] = f.w;
        }
        float2 f2 = reinterpret_cast<const float2*>(p)[14];
        e[28] = f2.x; e[29] = f2.y; e[30] = 0.f; e[31] = 0.f;
        #pragma unroll
        for (int j = 0; j < 16; j++)
            sE32[r * 16 + j] = pack_bf16x2(e[2 * j], e[2 * j + 1]);
    }
    // Copy x tile (17408 B) straight from device global
    #pragma unroll
    for (int i = tid; i < BB * XSTR_U32; i += 128)
        sX32[i] = g_xbf32[i];
    __syncthreads();

    // A fragments, persistent: [mtile][kchunk][reg]
    uint32_t a[2][2][4];
    {
        const int r0 = wid * 32 + grp;
        #pragma unroll
        for (int mt = 0; mt < 2; mt++) {
            #pragma unroll
            for (int kc = 0; kc < 2; kc++) {
                const int rr = r0 + mt * 16;
                const int cp = kc * 8 + qid;   // k-pair index
                a[mt][kc][0] = sE32[rr * 16 + cp];
                a[mt][kc][1] = sE32[(rr + 8) * 16 + cp];
                a[mt][kc][2] = sE32[rr * 16 + cp + 4];
                a[mt][kc][3] = sE32[(rr + 8) * 16 + cp + 4];
            }
        }
    }

    float* w = sW[wid];
    const int sw = qid << 3;              // STS swizzle key (= (b_local>>1)&3 << 3)

    #pragma unroll 1
    for (int pass = 0; pass < 8; pass++) {
        const int bp = pass * 32;

        // B fragments for this 32-b slab: [ntile][kchunk][reg]
        uint32_t bf[4][2][2];
        #pragma unroll
        for (int nt = 0; nt < 4; nt++) {
            const int bcol = bp + nt * 8 + grp;
            #pragma unroll
            for (int kc = 0; kc < 2; kc++) {
                bf[nt][kc][0] = sX32[bcol * XSTR_U32 + kc * 8 + qid];
                bf[nt][kc][1] = sX32[bcol * XSTR_U32 + kc * 8 + qid + 4];
            }
        }

        float acc[2][4][4];
        #pragma unroll
        for (int mt = 0; mt < 2; mt++)
            #pragma unroll
            for (int nt = 0; nt < 4; nt++)
                #pragma unroll
                for (int j = 0; j < 4; j++) acc[mt][nt][j] = 0.f;

        #pragma unroll
        for (int kc = 0; kc < 2; kc++)
            #pragma unroll
            for (int mt = 0; mt < 2; mt++)
                #pragma unroll
                for (int nt = 0; nt < 4; nt++)
                    mma_bf16(acc[mt][nt], a[mt][kc], bf[nt][kc]);

        // Stage sigmoid(acc) into the warp-private tile, XOR-swizzled.
        // Addr = b_local*32 + (v_local ^ (qid<<3)): banks injective per STS.
        #pragma unroll
        for (int mt = 0; mt < 2; mt++) {
            const int vl = grp + mt * 16;        // v_local of c0/c1; +8 for c2/c3
            #pragma unroll
            for (int nt = 0; nt < 4; nt++) {
                const int bl = nt * 8 + qid * 2; // b_local of c0/c2; +1 for c1/c3
                const float* c = acc[mt][nt];
                w[(bl + 0) * 32 + (vl ^ sw)]       = fast_sigmoid(c[0]);
                w[(bl + 1) * 32 + (vl ^ sw)]       = fast_sigmoid(c[1]);
                w[(bl + 0) * 32 + ((vl + 8) ^ sw)] = fast_sigmoid(c[2]);
                w[(bl + 1) * 32 + ((vl + 8) ^ sw)] = fast_sigmoid(c[3]);
            }
        }
        __syncwarp();

        // Drain: 8 x (LDS.128 + STG.128). Lane l: row r = j*4 + (l>>3),
        // cols (l&7)*4 .. +3 (XOR key (q<<3) only flips v bits 3-4, so the
        // float4 stays contiguous). Each quarter-phase of the LDS covers all
        // 32 banks once; each STG.128 writes 4 full 128B lines.
        {
            const int rsub = lane >> 3;          // 0..3
            const int csub = (lane & 7) * 4;     // 0,4,..28
            #pragma unroll
            for (int j = 0; j < 8; j++) {
                const int r = j * 4 + rsub;
                const int q = (r >> 1) & 3;
                const float4 val = *reinterpret_cast<const float4*>(
                    &w[r * 32 + (csub ^ (q << 3))]);
                stcs128(&out[(size_t)(bp + r) * VV + v0 + wid * 32 + csub], val);
            }
        }
        __syncwarp();
    }
}

// ---------------- launch ----------------
extern "C" void kernel_launch(void* const* d_in, const int* in_sizes, int n_in,
                              void* d_out, int out_size)
{
    (void)in_sizes; (void)n_in; (void)out_size;
    const int*   e1_idx = (const int*)  d_in[0];
    const int*   r_idx  = (const int*)  d_in[1];
    const float* E      = (const float*)d_in[2];
    const float* R      = (const float*)d_in[3];
    const float* proj   = (const float*)d_in[4];
    const int*   idx    = (const int*)  d_in[5];
    const float* g0     = (const float*)d_in[6];
    const float* b0     = (const float*)d_in[7];
    const float* m0     = (const float*)d_in[8];
    const float* v0     = (const float*)d_in[9];
    const float* g1     = (const float*)d_in[10];
    const float* b1     = (const float*)d_in[11];
    const float* m1     = (const float*)d_in[12];
    const float* v1     = (const float*)d_in[13];
    float*       out    = (float*)d_out;

    prep_kernel<<<BB, 64>>>(e1_idx, r_idx, E, R, proj, idx,
                            g0, b0, m0, v0, g1, b1, m1, v1);

    mma_kernel<<<VV / 128, 128>>>(E, out);   // 3125 CTAs
}

// round 12
// speedup vs baseline: 1.2362x; 1.1206x over previous
#include <cuda_runtime.h>
#include <cuda_bf16.h>
#include <cstdint>
#include <cstddef>

// Problem constants (LowFER)
#define BB 256          // batch
#define VV 400000       // vocab (= 3125 * 128)
#define D1 128
#define PP 64           // D1/2
#define KK 30
#define TT 20
#define BN_EPS 1e-5f
#define FACTOR 0.040824829046386304f   // 1/sqrt(K*T)

// x as bf16, permuted layout: row b (stride 16 u32), word p = qid*4 + (2*kc+j)
// holds k-pair c = kc*8 + qid + 4j. Zero-init covers k=30..31 (word p=15).
__device__ uint32_t g_x2[BB * 16];

// ---------------- helpers ----------------
__device__ __forceinline__ uint32_t pack_bf16x2(float lo, float hi) {
    uint32_t r;
    asm("cvt.rn.bf16x2.f32 %0, %1, %2;" : "=r"(r) : "f"(hi), "f"(lo));
    return r;
}
// sigmoid via ex2 + rcp (high accuracy, 2 MUFU)
__device__ __forceinline__ float fast_sigmoid(float z) {
    float e;
    asm("ex2.approx.f32 %0, %1;" : "=f"(e) : "f"(-z * 1.4426950408889634f));
    float r;
    asm("rcp.approx.f32 %0, %1;" : "=f"(r) : "f"(1.0f + e));
    return r;
}
// streaming store (evict-first): output is write-once
__device__ __forceinline__ void stcs128(float* p, float4 v) {
    asm volatile("st.global.cs.v4.f32 [%0], {%1,%2,%3,%4};"
                 :: "l"(p), "f"(v.x), "f"(v.y), "f"(v.z), "f"(v.w) : "memory");
}
// m16n8k16 bf16 x bf16 -> f32 (sm_80+ base feature)
__device__ __forceinline__ void mma_bf16(float* c, const uint32_t* a, const uint32_t* b) {
    asm volatile(
        "mma.sync.aligned.m16n8k16.row.col.f32.bf16.bf16.f32 "
        "{%0,%1,%2,%3}, {%4,%5,%6,%7}, {%8,%9}, {%0,%1,%2,%3};"
        : "+f"(c[0]), "+f"(c[1]), "+f"(c[2]), "+f"(c[3])
        : "r"(a[0]), "r"(a[1]), "r"(a[2]), "r"(a[3]), "r"(b[0]), "r"(b[1]));
}

// ---------------- Kernel 1: compute x, store bf16 permuted [b][p] ----------------
__global__ void prep_kernel(const int* __restrict__ e1_idx, const int* __restrict__ r_idx,
                            const float* __restrict__ E,   const float* __restrict__ R,
                            const float* __restrict__ proj, const int* __restrict__ idx,
                            const float* __restrict__ g0, const float* __restrict__ b0,
                            const float* __restrict__ m0, const float* __restrict__ v0,
                            const float* __restrict__ g1, const float* __restrict__ b1,
                            const float* __restrict__ m1, const float* __restrict__ v1)
{
    __shared__ float e1s[D1];
    __shared__ float rrs[D1];
    __shared__ float ses[PP];
    __shared__ float srs[PP];

    const int t = threadIdx.x;     // 0..63
    const int b = blockIdx.x;      // 0..255

    const int ei = e1_idx[b];
    const int ri = r_idx[b];

    #pragma unroll
    for (int j = 0; j < 2; j++) {
        const int d = t + j * 64;
        float ev = E[(size_t)ei * D1 + d];
        e1s[d] = (ev - m0[d]) * rsqrtf(v0[d] + BN_EPS) * g0[d] + b0[d];
        rrs[d] = R[(size_t)ri * D1 + d];
    }
    __syncthreads();

    float sa = 0.f, sb = 0.f;
    #pragma unroll 16
    for (int d = 0; d < D1; d++) {
        const float p = proj[d * PP + t];
        sa = fmaf(e1s[d], p, sa);
        sb = fmaf(rrs[d], p, sb);
    }
    ses[t] = sa;
    srs[t] = sb;
    __syncthreads();

    float x = 0.f;
    if (t < KK) {
        float y = 0.f;
        #pragma unroll
        for (int tt = 0; tt < TT; tt++) {
            const int ia = idx[(t * TT + tt) * 2 + 0];
            const int ib = idx[(t * TT + tt) * 2 + 1];
            y = fmaf(ses[ia], srs[ib], y);
        }
        y *= FACTOR;
        const float sg = (y > 0.f) ? 1.f : ((y < 0.f) ? -1.f : 0.f);
        x = sg * sqrtf(fabsf(y) + 1e-12f);
    }

    if (t < 32) {
        float ss = x * x;
        #pragma unroll
        for (int o = 16; o; o >>= 1) ss += __shfl_xor_sync(0xffffffffu, ss, o);
        const float nrm = sqrtf(ss);
        float xn = 0.f;
        if (t < KK) {
            xn = x / fmaxf(nrm, 1e-12f);
            xn = (xn - m1[t]) * rsqrtf(v1[t] + BN_EPS) * g1[t] + b1[t];
            // permuted store: k = t -> k-pair c = t/2, half = t&1
            // word p: qid = c & 3, kc = c >> 3, j = (c >> 2) & 1
            const int c  = t >> 1;
            const int p  = (c & 3) * 4 + ((c >> 3) << 1) + ((c >> 2) & 1);
            __nv_bfloat16* xb = reinterpret_cast<__nv_bfloat16*>(g_x2);
            xb[b * 32 + p * 2 + (t & 1)] = __float2bfloat16(xn);
        }
    }
}

// ---------------- Kernel 2: warp-level bf16 MMA, unioned smem, LDS.128 B-frags ---
// CTA: 128 threads (4 warps). M=128 v (32/warp), N=256 b in 8 passes of 32.
// smem: sU (16KB) = sE (8KB, prolog only) UNION sW staging (4x4KB, mainloop);
//       sX (16KB) = permuted x2 rows, enabling 4x conflict-free LDS.128 per pass.
__global__ __launch_bounds__(128, 6)
void mma_kernel(const float* __restrict__ E, float* __restrict__ out)
{
    __shared__ uint32_t sU[4096];          // 16 KB union: sE32 (first 8KB) / sW
    __shared__ uint32_t sX[BB * 16];       // 16 KB, permuted x2

    const int tid  = threadIdx.x;
    const int wid  = tid >> 5;
    const int lane = tid & 31;
    const int grp  = lane >> 2;   // 0..7
    const int qid  = lane & 3;    // 0..3

    const int v0 = blockIdx.x * 128;

    // Build sE (rows [v][16 k-pair words]) in the union's first 8 KB
    {
        const int r = tid;
        const float4* p = reinterpret_cast<const float4*>(E + (size_t)(v0 + r) * D1);
        float e[32];
        #pragma unroll
        for (int q = 0; q < 7; q++) {
            float4 f = p[q];
            e[q * 4 + 0] = f.x; e[q * 4 + 1] = f.y;
            e[q * 4 + 2] = f.z; e[q * 4 + 3] = f.w;
        }
        float2 f2 = reinterpret_cast<const float2*>(p)[14];
        e[28] = f2.x; e[29] = f2.y; e[30] = 0.f; e[31] = 0.f;
        #pragma unroll
        for (int j = 0; j < 16; j++)
            sU[r * 16 + j] = pack_bf16x2(e[2 * j], e[2 * j + 1]);
    }
    // Copy permuted x tile (16 KB contiguous)
    #pragma unroll
    for (int i = 0; i < (BB * 16) / 128; i++)
        sX[i * 128 + tid] = g_x2[i * 128 + tid];
    __syncthreads();

    // A fragments, persistent: [mtile][kchunk][reg]
    uint32_t a[2][2][4];
    {
        const int r0 = wid * 32 + grp;
        #pragma unroll
        for (int mt = 0; mt < 2; mt++) {
            #pragma unroll
            for (int kc = 0; kc < 2; kc++) {
                const int rr = r0 + mt * 16;
                const int cp = kc * 8 + qid;   // k-pair index
                a[mt][kc][0] = sU[rr * 16 + cp];
                a[mt][kc][1] = sU[(rr + 8) * 16 + cp];
                a[mt][kc][2] = sU[rr * 16 + cp + 4];
                a[mt][kc][3] = sU[(rr + 8) * 16 + cp + 4];
            }
        }
    }
    __syncthreads();   // all A-frags read; union region becomes staging sW

    float* w = reinterpret_cast<float*>(sU) + wid * 1024;   // 4 KB per warp
    const int sw = qid << 3;              // STS swizzle key

    #pragma unroll 1
    for (int pass = 0; pass < 8; pass++) {
        const int bp = pass * 32;

        // B fragments: one LDS.128 per nt; lane (grp,qid) reads
        // sX[(bp+nt*8+grp)*16 + qid*4 .. +3]  (phase-wise all 32 banks: CF).
        // float4 regs map: [0]=kc0 j0, [1]=kc0 j1, [2]=kc1 j0, [3]=kc1 j1.
        uint32_t bf[4][2][2];
        #pragma unroll
        for (int nt = 0; nt < 4; nt++) {
            const uint4 f = *reinterpret_cast<const uint4*>(
                &sX[(bp + nt * 8 + grp) * 16 + qid * 4]);
            bf[nt][0][0] = f.x;  bf[nt][0][1] = f.y;
            bf[nt][1][0] = f.z;  bf[nt][1][1] = f.w;
        }

        float acc[2][4][4];
        #pragma unroll
        for (int mt = 0; mt < 2; mt++)
            #pragma unroll
            for (int nt = 0; nt < 4; nt++)
                #pragma unroll
                for (int j = 0; j < 4; j++) acc[mt][nt][j] = 0.f;

        #pragma unroll
        for (int kc = 0; kc < 2; kc++)
            #pragma unroll
            for (int mt = 0; mt < 2; mt++)
                #pragma unroll
                for (int nt = 0; nt < 4; nt++)
                    mma_bf16(acc[mt][nt], a[mt][kc], bf[nt][kc]);

        // Stage sigmoid(acc) into the warp-private tile, XOR-swizzled.
        #pragma unroll
        for (int mt = 0; mt < 2; mt++) {
            const int vl = grp + mt * 16;        // v_local of c0/c1; +8 for c2/c3
            #pragma unroll
            for (int nt = 0; nt < 4; nt++) {
                const int bl = nt * 8 + qid * 2; // b_local of c0/c2; +1 for c1/c3
                const float* c = acc[mt][nt];
                w[(bl + 0) * 32 + (vl ^ sw)]       = fast_sigmoid(c[0]);
                w[(bl + 1) * 32 + (vl ^ sw)]       = fast_sigmoid(c[1]);
                w[(bl + 0) * 32 + ((vl + 8) ^ sw)] = fast_sigmoid(c[2]);
                w[(bl + 1) * 32 + ((vl + 8) ^ sw)] = fast_sigmoid(c[3]);
            }
        }
        __syncwarp();

        // Drain: 8 x (LDS.128 + STG.128); each STG writes 4 full 128B lines.
        {
            const int rsub = lane >> 3;          // 0..3
            const int csub = (lane & 7) * 4;     // 0,4,..28
            #pragma unroll
            for (int j = 0; j < 8; j++) {
                const int r = j * 4 + rsub;
                const int q = (r >> 1) & 3;
                const float4 val = *reinterpret_cast<const float4*>(
                    &w[r * 32 + (csub ^ (q << 3))]);
                stcs128(&out[(size_t)(bp + r) * VV + v0 + wid * 32 + csub], val);
            }
        }
        __syncwarp();
    }
}

// ---------------- launch ----------------
extern "C" void kernel_launch(void* const* d_in, const int* in_sizes, int n_in,
                              void* d_out, int out_size)
{
    (void)in_sizes; (void)n_in; (void)out_size;
    const int*   e1_idx = (const int*)  d_in[0];
    const int*   r_idx  = (const int*)  d_in[1];
    const float* E      = (const float*)d_in[2];
    const float* R      = (const float*)d_in[3];
    const float* proj   = (const float*)d_in[4];
    const int*   idx    = (const int*)  d_in[5];
    const float* g0     = (const float*)d_in[6];
    const float* b0     = (const float*)d_in[7];
    const float* m0     = (const float*)d_in[8];
    const float* v0     = (const float*)d_in[9];
    const float* g1     = (const float*)d_in[10];
    const float* b1     = (const float*)d_in[11];
    const float* m1     = (const float*)d_in[12];
    const float* v1     = (const float*)d_in[13];
    float*       out    = (float*)d_out;

    prep_kernel<<<BB, 64>>>(e1_idx, r_idx, E, R, proj, idx,
                            g0, b0, m0, v0, g1, b1, m1, v1);

    mma_kernel<<<VV / 128, 128>>>(E, out);   // 3125 CTAs
}

// round 13
// speedup vs baseline: 1.3680x; 1.1066x over previous
#include <cuda_runtime.h>
#include <cuda_bf16.h>
#include <cstdint>
#include <cstddef>

// Problem constants (LowFER)
#define BB 256          // batch
#define VV 400000       // vocab (= 3125 * 128)
#define D1 128
#define PP 64           // D1/2
#define KK 30
#define TT 20
#define BN_EPS 1e-5f
#define FACTOR 0.040824829046386304f   // 1/sqrt(K*T)

// x as bf16, permuted layout: row b (stride 16 u32), word p = qid*4 + (2*kc+j)
// holds k-pair c = kc*8 + qid + 4j. Zero-init covers k=30..31 (word p=15).
__device__ uint32_t g_x2[BB * 16];

// ---------------- helpers ----------------
__device__ __forceinline__ uint32_t pack_bf16x2(float lo, float hi) {
    uint32_t r;
    asm("cvt.rn.bf16x2.f32 %0, %1, %2;" : "=r"(r) : "f"(hi), "f"(lo));
    return r;
}
// sigmoid via ex2 + rcp (high accuracy, 2 MUFU)
__device__ __forceinline__ float fast_sigmoid(float z) {
    float e;
    asm("ex2.approx.f32 %0, %1;" : "=f"(e) : "f"(-z * 1.4426950408889634f));
    float r;
    asm("rcp.approx.f32 %0, %1;" : "=f"(r) : "f"(1.0f + e));
    return r;
}
// streaming store (evict-first): output is write-once
__device__ __forceinline__ void stcs128(float* p, float4 v) {
    asm volatile("st.global.cs.v4.f32 [%0], {%1,%2,%3,%4};"
                 :: "l"(p), "f"(v.x), "f"(v.y), "f"(v.z), "f"(v.w) : "memory");
}
// m16n8k16 bf16 x bf16 -> f32 (sm_80+ base feature)
__device__ __forceinline__ void mma_bf16(float* c, const uint32_t* a, const uint32_t* b) {
    asm volatile(
        "mma.sync.aligned.m16n8k16.row.col.f32.bf16.bf16.f32 "
        "{%0,%1,%2,%3}, {%4,%5,%6,%7}, {%8,%9}, {%0,%1,%2,%3};"
        : "+f"(c[0]), "+f"(c[1]), "+f"(c[2]), "+f"(c[3])
        : "r"(a[0]), "r"(a[1]), "r"(a[2]), "r"(a[3]), "r"(b[0]), "r"(b[1]));
}

// ---------------- Kernel 1: compute x, store bf16 permuted [b][p] ----------------
__global__ void prep_kernel(const int* __restrict__ e1_idx, const int* __restrict__ r_idx,
                            const float* __restrict__ E,   const float* __restrict__ R,
                            const float* __restrict__ proj, const int* __restrict__ idx,
                            const float* __restrict__ g0, const float* __restrict__ b0,
                            const float* __restrict__ m0, const float* __restrict__ v0,
                            const float* __restrict__ g1, const float* __restrict__ b1,
                            const float* __restrict__ m1, const float* __restrict__ v1)
{
    __shared__ float e1s[D1];
    __shared__ float rrs[D1];
    __shared__ float ses[PP];
    __shared__ float srs[PP];

    const int t = threadIdx.x;     // 0..63
    const int b = blockIdx.x;      // 0..255

    const int ei = e1_idx[b];
    const int ri = r_idx[b];

    #pragma unroll
    for (int j = 0; j < 2; j++) {
        const int d = t + j * 64;
        float ev = E[(size_t)ei * D1 + d];
        e1s[d] = (ev - m0[d]) * rsqrtf(v0[d] + BN_EPS) * g0[d] + b0[d];
        rrs[d] = R[(size_t)ri * D1 + d];
    }
    __syncthreads();

    float sa = 0.f, sb = 0.f;
    #pragma unroll 16
    for (int d = 0; d < D1; d++) {
        const float p = proj[d * PP + t];
        sa = fmaf(e1s[d], p, sa);
        sb = fmaf(rrs[d], p, sb);
    }
    ses[t] = sa;
    srs[t] = sb;
    __syncthreads();

    float x = 0.f;
    if (t < KK) {
        float y = 0.f;
        #pragma unroll
        for (int tt = 0; tt < TT; tt++) {
            const int ia = idx[(t * TT + tt) * 2 + 0];
            const int ib = idx[(t * TT + tt) * 2 + 1];
            y = fmaf(ses[ia], srs[ib], y);
        }
        y *= FACTOR;
        const float sg = (y > 0.f) ? 1.f : ((y < 0.f) ? -1.f : 0.f);
        x = sg * sqrtf(fabsf(y) + 1e-12f);
    }

    if (t < 32) {
        float ss = x * x;
        #pragma unroll
        for (int o = 16; o; o >>= 1) ss += __shfl_xor_sync(0xffffffffu, ss, o);
        const float nrm = sqrtf(ss);
        float xn = 0.f;
        if (t < KK) {
            xn = x / fmaxf(nrm, 1e-12f);
            xn = (xn - m1[t]) * rsqrtf(v1[t] + BN_EPS) * g1[t] + b1[t];
            // permuted store: k = t -> k-pair c = t/2, half = t&1
            // word p: qid = c & 3, kc = c >> 3, j = (c >> 2) & 1
            const int c  = t >> 1;
            const int p  = (c & 3) * 4 + ((c >> 3) << 1) + ((c >> 2) & 1);
            __nv_bfloat16* xb = reinterpret_cast<__nv_bfloat16*>(g_x2);
            xb[b * 32 + p * 2 + (t & 1)] = __float2bfloat16(xn);
        }
    }
}

// ---------------- Kernel 2: bf16 MMA, B-frags via L1-resident LDG, low-reg -------
// CTA: 128 threads (4 warps). M=128 v (32/warp), N=256 b in 8 passes of 32.
// smem: 16 KB only (sE prolog UNION per-warp staging). B-fragments read from
// g_x2 (16 KB device global, L1-resident). Early epilogue: each (mt,nt) subtile
// is MMA'd, sigmoided, and staged immediately -> only 4 acc floats live.
__global__ __launch_bounds__(128, 7)
void mma_kernel(const float* __restrict__ E, float* __restrict__ out)
{
    __shared__ uint32_t sU[4096];          // 16 KB union: sE32 (first 8KB) / sW

    const int tid  = threadIdx.x;
    const int wid  = tid >> 5;
    const int lane = tid & 31;
    const int grp  = lane >> 2;   // 0..7
    const int qid  = lane & 3;    // 0..3

    const int v0 = blockIdx.x * 128;

    // Build sE (rows [v][16 k-pair words]) in the union's first 8 KB.
    // Row r is written by tid == r and A-frags read only own-warp rows
    // -> __syncwarp suffices here.
    {
        const int r = tid;
        const float4* p = reinterpret_cast<const float4*>(E + (size_t)(v0 + r) * D1);
        float e[32];
        #pragma unroll
        for (int q = 0; q < 7; q++) {
            float4 f = p[q];
            e[q * 4 + 0] = f.x; e[q * 4 + 1] = f.y;
            e[q * 4 + 2] = f.z; e[q * 4 + 3] = f.w;
        }
        float2 f2 = reinterpret_cast<const float2*>(p)[14];
        e[28] = f2.x; e[29] = f2.y; e[30] = 0.f; e[31] = 0.f;
        #pragma unroll
        for (int j = 0; j < 16; j++)
            sU[r * 16 + j] = pack_bf16x2(e[2 * j], e[2 * j + 1]);
    }
    __syncwarp();

    // A fragments, persistent: [mtile][kchunk][reg]
    uint32_t a[2][2][4];
    {
        const int r0 = wid * 32 + grp;
        #pragma unroll
        for (int mt = 0; mt < 2; mt++) {
            #pragma unroll
            for (int kc = 0; kc < 2; kc++) {
                const int rr = r0 + mt * 16;
                const int cp = kc * 8 + qid;   // k-pair index
                a[mt][kc][0] = sU[rr * 16 + cp];
                a[mt][kc][1] = sU[(rr + 8) * 16 + cp];
                a[mt][kc][2] = sU[rr * 16 + cp + 4];
                a[mt][kc][3] = sU[(rr + 8) * 16 + cp + 4];
            }
        }
    }
    __syncthreads();   // all warps' A-frags read; union region becomes staging

    float* w = reinterpret_cast<float*>(sU) + wid * 1024;   // 4 KB per warp
    const int sw = qid << 3;              // STS swizzle key

    #pragma unroll 1
    for (int pass = 0; pass < 8; pass++) {
        const int bp = pass * 32;

        // B fragments straight from global (L1-resident, 16 KB total):
        // lane (grp,qid) reads g_x2[(bp+nt*8+grp)*16 + qid*4 .. +3].
        uint32_t bf[4][2][2];
        #pragma unroll
        for (int nt = 0; nt < 4; nt++) {
            const uint4 f = *reinterpret_cast<const uint4*>(
                &g_x2[(bp + nt * 8 + grp) * 16 + qid * 4]);
            bf[nt][0][0] = f.x;  bf[nt][0][1] = f.y;
            bf[nt][1][0] = f.z;  bf[nt][1][1] = f.w;
        }

        // Early epilogue: finish each (mt,nt) subtile immediately (4 live acc).
        #pragma unroll
        for (int mt = 0; mt < 2; mt++) {
            const int vl = grp + mt * 16;        // v_local of c0/c1; +8 for c2/c3
            #pragma unroll
            for (int nt = 0; nt < 4; nt++) {
                float acc[4] = {0.f, 0.f, 0.f, 0.f};
                mma_bf16(acc, a[mt][0], bf[nt][0]);
                mma_bf16(acc, a[mt][1], bf[nt][1]);
                const int bl = nt * 8 + qid * 2; // b_local of c0/c2; +1 for c1/c3
                w[(bl + 0) * 32 + (vl ^ sw)]       = fast_sigmoid(acc[0]);
                w[(bl + 1) * 32 + (vl ^ sw)]       = fast_sigmoid(acc[1]);
                w[(bl + 0) * 32 + ((vl + 8) ^ sw)] = fast_sigmoid(acc[2]);
                w[(bl + 1) * 32 + ((vl + 8) ^ sw)] = fast_sigmoid(acc[3]);
            }
        }
        __syncwarp();

        // Drain: 8 x (LDS.128 + STG.128); each STG writes 4 full 128B lines.
        {
            const int rsub = lane >> 3;          // 0..3
            const int csub = (lane & 7) * 4;     // 0,4,..28
            #pragma unroll
            for (int j = 0; j < 8; j++) {
                const int r = j * 4 + rsub;
                const int q = (r >> 1) & 3;
                const float4 val = *reinterpret_cast<const float4*>(
                    &w[r * 32 + (csub ^ (q << 3))]);
                stcs128(&out[(size_t)(bp + r) * VV + v0 + wid * 32 + csub], val);
            }
        }
        __syncwarp();
    }
}

// ---------------- launch ----------------
extern "C" void kernel_launch(void* const* d_in, const int* in_sizes, int n_in,
                              void* d_out, int out_size)
{
    (void)in_sizes; (void)n_in; (void)out_size;
    const int*   e1_idx = (const int*)  d_in[0];
    const int*   r_idx  = (const int*)  d_in[1];
    const float* E      = (const float*)d_in[2];
    const float* R      = (const float*)d_in[3];
    const float* proj   = (const float*)d_in[4];
    const int*   idx    = (const int*)  d_in[5];
    const float* g0     = (const float*)d_in[6];
    const float* b0     = (const float*)d_in[7];
    const float* m0     = (const float*)d_in[8];
    const float* v0     = (const float*)d_in[9];
    const float* g1     = (const float*)d_in[10];
    const float* b1     = (const float*)d_in[11];
    const float* m1     = (const float*)d_in[12];
    const float* v1     = (const float*)d_in[13];
    float*       out    = (float*)d_out;

    prep_kernel<<<BB, 64>>>(e1_idx, r_idx, E, R, proj, idx,
                            g0, b0, m0, v0, g1, b1, m1, v1);

    mma_kernel<<<VV / 128, 128>>>(E, out);   // 3125 CTAs
}